// round 1
// baseline (speedup 1.0000x reference)
#include <cuda_runtime.h>
#include <math.h>

// Flash-attention fp32 baseline for [B=4,H=16,S=2048,D=128] SDPA.
// BM=64 q-rows per CTA, BN=64 k-rows per tile, 128 threads.
// Per-thread: 8x4 score tile, 8x8 output tile.

#define DHEAD     128
#define D4        (DHEAD / 4)   // 32 float4 per row
#define BM        64
#define BN        64
#define NTHREADS  128

// (1/sqrt(128)) * log2(e)
#define SCALE_LOG2E 0.12751743835f

__device__ __forceinline__ float fast_exp2(float x) {
    float y;
    asm("ex2.approx.ftz.f32 %0, %1;" : "=f"(y) : "f"(x));
    return y;
}

// XOR swizzle on the float4-column index, keyed by row bits [2:5).
// Makes both the row-major store (one row per warp) and the strided
// column reads (16 lanes, rows 4*tx+c) bank-conflict-light.
__device__ __forceinline__ int swz(int r, int c4) {
    return r * D4 + (c4 ^ ((r >> 2) & 7));
}

__global__ __launch_bounds__(NTHREADS, 2)
void sdpa_fp32_kernel(const float* __restrict__ Q,
                      const float* __restrict__ K,
                      const float* __restrict__ V,
                      float* __restrict__ O,
                      int S)
{
    extern __shared__ float smem[];
    float4* Qs = (float4*)smem;            // BM * D4 float4 (32 KB)
    float4* Ks = Qs + BM * D4;             // BN * D4 float4 (32 KB)
    float4* Vs = Ks + BN * D4;             // BN * D4 float4 (32 KB)
    float*  Ps = (float*)(Vs + BN * D4);   // BM * BN floats (16 KB)

    const int tid = threadIdx.x;
    const int tx  = tid & 15;   // 0..15  -> score cols 4*tx.., out cols 8*tx..
    const int ty  = tid >> 4;   // 0..7   -> rows 8*ty..8*ty+7

    const size_t bh = blockIdx.y;
    const int    q0 = blockIdx.x * BM;

    const float4* Qg = (const float4*)(Q + (bh * (size_t)S + q0) * DHEAD);
    const float4* Kg = (const float4*)(K + bh * (size_t)S * DHEAD);
    const float4* Vg = (const float4*)(V + bh * (size_t)S * DHEAD);

    // ---- load Q tile once (coalesced, swizzled) ----
    #pragma unroll
    for (int i = tid; i < BM * D4; i += NTHREADS) {
        int r = i >> 5, c = i & 31;
        Qs[swz(r, c)] = Qg[i];
    }

    // ---- per-thread state ----
    float o[8][8];
    float m[8], l[8];
    #pragma unroll
    for (int r = 0; r < 8; r++) {
        m[r] = -INFINITY;
        l[r] = 0.0f;
        #pragma unroll
        for (int c = 0; c < 8; c++) o[r][c] = 0.0f;
    }

    const int ntiles = S / BN;
    for (int j = 0; j < ntiles; j++) {
        const float4* Kt = Kg + (size_t)j * BN * D4;
        const float4* Vt = Vg + (size_t)j * BN * D4;

        __syncthreads();   // previous PV reads of Ks/Vs done
        #pragma unroll
        for (int i = tid; i < BN * D4; i += NTHREADS) {
            int r = i >> 5, c = i & 31;
            int idx = swz(r, c);
            Ks[idx] = Kt[i];
            Vs[idx] = Vt[i];
        }
        __syncthreads();

        // ---- S = Q K^T  (8x4 per thread) ----
        float s[8][4];
        #pragma unroll
        for (int r = 0; r < 8; r++)
            #pragma unroll
            for (int c = 0; c < 4; c++) s[r][c] = 0.0f;

        #pragma unroll 4
        for (int k4 = 0; k4 < D4; k4++) {
            float4 qv[8], kv[4];
            #pragma unroll
            for (int r = 0; r < 8; r++) qv[r] = Qs[swz(8 * ty + r, k4)];
            #pragma unroll
            for (int c = 0; c < 4; c++) kv[c] = Ks[swz(4 * tx + c, k4)];
            #pragma unroll
            for (int r = 0; r < 8; r++) {
                #pragma unroll
                for (int c = 0; c < 4; c++) {
                    s[r][c] += qv[r].x * kv[c].x;
                    s[r][c] += qv[r].y * kv[c].y;
                    s[r][c] += qv[r].z * kv[c].z;
                    s[r][c] += qv[r].w * kv[c].w;
                }
            }
        }

        // ---- online softmax (base-2 domain) + stage P in smem ----
        #pragma unroll
        for (int r = 0; r < 8; r++) {
            float mx = fmaxf(fmaxf(s[r][0], s[r][1]), fmaxf(s[r][2], s[r][3]));
            #pragma unroll
            for (int msk = 1; msk < 16; msk <<= 1)
                mx = fmaxf(mx, __shfl_xor_sync(0xffffffffu, mx, msk));

            float mnew  = fmaxf(m[r], mx * SCALE_LOG2E);
            float alpha = fast_exp2(m[r] - mnew);   // exp2(-inf)=0 on first tile
            m[r] = mnew;

            float p0 = fast_exp2(s[r][0] * SCALE_LOG2E - mnew);
            float p1 = fast_exp2(s[r][1] * SCALE_LOG2E - mnew);
            float p2 = fast_exp2(s[r][2] * SCALE_LOG2E - mnew);
            float p3 = fast_exp2(s[r][3] * SCALE_LOG2E - mnew);

            float rs = (p0 + p1) + (p2 + p3);
            #pragma unroll
            for (int msk = 1; msk < 16; msk <<= 1)
                rs += __shfl_xor_sync(0xffffffffu, rs, msk);

            l[r] = l[r] * alpha + rs;
            #pragma unroll
            for (int c = 0; c < 8; c++) o[r][c] *= alpha;

            float4 pq = make_float4(p0, p1, p2, p3);
            *(float4*)&Ps[(8 * ty + r) * BN + 4 * tx] = pq;
        }
        __syncthreads();

        // ---- O += P V  (8 rows x 8 cols per thread) ----
        #pragma unroll 4
        for (int kk4 = 0; kk4 < BN / 4; kk4++) {
            float4 pv[8];
            #pragma unroll
            for (int r = 0; r < 8; r++)
                pv[r] = *(const float4*)&Ps[(8 * ty + r) * BN + 4 * kk4];

            #pragma unroll
            for (int kk = 0; kk < 4; kk++) {
                int row = 4 * kk4 + kk;
                float4 v0 = Vs[swz(row, 2 * tx)];
                float4 v1 = Vs[swz(row, 2 * tx + 1)];
                #pragma unroll
                for (int r = 0; r < 8; r++) {
                    float p = (kk == 0) ? pv[r].x : (kk == 1) ? pv[r].y
                            : (kk == 2) ? pv[r].z : pv[r].w;
                    o[r][0] += p * v0.x;  o[r][1] += p * v0.y;
                    o[r][2] += p * v0.z;  o[r][3] += p * v0.w;
                    o[r][4] += p * v1.x;  o[r][5] += p * v1.y;
                    o[r][6] += p * v1.z;  o[r][7] += p * v1.w;
                }
            }
        }
    }

    // ---- epilogue: normalize and store ----
    #pragma unroll
    for (int r = 0; r < 8; r++) {
        float inv = 1.0f / l[r];
        float4* Og = (float4*)(O + (bh * (size_t)S + q0 + 8 * ty + r) * DHEAD);
        float4 a = make_float4(o[r][0] * inv, o[r][1] * inv, o[r][2] * inv, o[r][3] * inv);
        float4 b = make_float4(o[r][4] * inv, o[r][5] * inv, o[r][6] * inv, o[r][7] * inv);
        Og[2 * tx]     = a;
        Og[2 * tx + 1] = b;
    }
}

extern "C" void kernel_launch(void* const* d_in, const int* in_sizes, int n_in,
                              void* d_out, int out_size)
{
    const float* q = (const float*)d_in[0];
    const float* k = (const float*)d_in[1];
    const float* v = (const float*)d_in[2];
    float* o = (float*)d_out;

    const int S  = 2048;
    const int BH = in_sizes[0] / (S * DHEAD);   // 64

    size_t smem = (size_t)(BM * DHEAD + 2 * BN * DHEAD + BM * BN) * sizeof(float); // 114688
    cudaFuncSetAttribute(sdpa_fp32_kernel,
                         cudaFuncAttributeMaxDynamicSharedMemorySize, (int)smem);

    dim3 grid(S / BM, BH);
    sdpa_fp32_kernel<<<grid, NTHREADS, smem>>>(q, k, v, o, S);
}

// round 3
// speedup vs baseline: 3.1301x; 3.1301x over previous
#include <cuda_runtime.h>
#include <cstdint>
#include <math.h>

#define DH      128
#define BM      128
#define BN      64
#define NT      256
#define SL      2048
#define NTILES  (SL / BN)

// p = exp2(s * C1 - M2) == exp(s/sqrt(128) - 16)
#define C1f 0.12751744154f
#define M2f 23.083120654f

// ---- SMEM layout (float offsets), fragment-permuted operand layouts ----
// Element (row, kcol) with kcol = 8*ks + 4*p + c (c in 0..3, p in 0..1)
// lives at  base + ks*STRIDE + row*8 + 2*c + p.
#define QS_KS 1028               // 128*8 + 4 pad
#define KS_KS 516                // 64*8 + 4 pad
#define VS_KS 1028
#define PS_KS 1028
#define Q_OFF 0
#define K_OFF (16 * QS_KS)              // 16448
#define V_OFF (K_OFF + 16 * KS_KS)      // 24704
#define P_OFF (V_OFF + 8 * VS_KS)       // 32928
#define SMEM_FLOATS (P_OFF + 8 * PS_KS) // 41152
#define SMEM_BYTES  (SMEM_FLOATS * 4)   // 164608

static __device__ __forceinline__ float to_tf32(float x) {
    uint32_t u;
    asm("cvt.rna.tf32.f32 %0, %1;" : "=r"(u) : "f"(x));
    return __uint_as_float(u);
}
// exp2 for x <= 0 (clamped >= -100): magic-round + degree-4 poly, fma/alu only
static __device__ __forceinline__ float exp2_fast(float x) {
    float t  = x + 12582912.0f;
    float fi = t - 12582912.0f;
    float f  = x - fi;
    int   n  = __float_as_int(t) - 0x4B400000;
    float p  = 0.0096181382f;
    p = fmaf(p, f, 0.0555041087f);
    p = fmaf(p, f, 0.2402265070f);
    p = fmaf(p, f, 0.6931471806f);
    p = fmaf(p, f, 1.0f);
    return __int_as_float(__float_as_int(p) + (n << 23));
}

// D/C fp32, A/B tf32 (b32 regs), m16n8k8
static __device__ __forceinline__ void mma_tf32(float* d,
                                                uint32_t a0, uint32_t a1, uint32_t a2, uint32_t a3,
                                                uint32_t b0, uint32_t b1) {
    asm volatile("mma.sync.aligned.m16n8k8.row.col.f32.tf32.tf32.f32 "
                 "{%0,%1,%2,%3}, {%4,%5,%6,%7}, {%8,%9}, {%0,%1,%2,%3};"
                 : "+f"(d[0]), "+f"(d[1]), "+f"(d[2]), "+f"(d[3])
                 : "r"(a0), "r"(a1), "r"(a2), "r"(a3), "r"(b0), "r"(b1));
}

__global__ __launch_bounds__(NT, 1)
void sdpa_mma_kernel(const float* __restrict__ Q,
                     const float* __restrict__ K,
                     const float* __restrict__ V,
                     float* __restrict__ Out)
{
    extern __shared__ float smf[];
    const int tid  = threadIdx.x;
    const int wid  = tid >> 5;
    const int lane = tid & 31;
    const int qd   = lane >> 2;   // 0..7  (fragment row group)
    const int qr   = lane & 3;    // 0..3  (fragment col group)
    const int wm0  = wid * 16;    // warp's 16-row M slice

    const size_t bh = blockIdx.y;
    const int    q0 = blockIdx.x * BM;
    const float4* Qg4 = (const float4*)(Q + (bh * SL + q0) * DH);
    const float4* Kg4 = (const float4*)(K + bh * SL * DH);
    const float4* Vg4 = (const float4*)(V + bh * SL * DH);

    // ---- Q prologue: GMEM -> tf32 -> permuted SMEM ----
    #pragma unroll
    for (int it = 0; it < 16; it++) {
        int i = tid + it * NT;
        int m = i >> 5, j = i & 31;            // j = d/4
        float4 v = Qg4[i];
        int base = Q_OFF + (j >> 1) * QS_KS + m * 8 + (j & 1);
        smf[base]     = to_tf32(v.x);
        smf[base + 2] = to_tf32(v.y);
        smf[base + 4] = to_tf32(v.z);
        smf[base + 6] = to_tf32(v.w);
    }

    float oacc[16][4];
    #pragma unroll
    for (int n = 0; n < 16; n++)
        #pragma unroll
        for (int e = 0; e < 4; e++) oacc[n][e] = 0.0f;
    float l0 = 0.0f, l1 = 0.0f;

    for (int t = 0; t < NTILES; t++) {
        __syncthreads();   // previous PV reads of Vp done; Kp free
        // ---- stage K tile ----
        const float4* Kt = Kg4 + (size_t)(t * BN) * (DH / 4);
        #pragma unroll
        for (int it = 0; it < 8; it++) {
            int i = tid + it * NT;
            int n = i >> 5, j = i & 31;
            float4 v = Kt[i];
            int base = K_OFF + (j >> 1) * KS_KS + n * 8 + (j & 1);
            smf[base]     = to_tf32(v.x);
            smf[base + 2] = to_tf32(v.y);
            smf[base + 4] = to_tf32(v.z);
            smf[base + 6] = to_tf32(v.w);
        }
        // ---- stage V tile (k-dim = position), XOR-swizzled to avoid STS conflicts ----
        const float4* Vt = Vg4 + (size_t)(t * BN) * (DH / 4);
        #pragma unroll
        for (int it = 0; it < 8; it++) {
            int i = tid + it * NT;
            int pos = i >> 5, j = i & 31;      // j = d/4
            float4 v = Vt[i];
            int ksp = pos >> 3;
            int kh = (j & 3) << 3;
            int kl = ((j >> 2) & 3) << 1;
            int vb = V_OFF + ksp * VS_KS + 32 * j
                   + (((pos & 3) << 1) ^ kl) + ((pos >> 2) & 1);
            smf[vb + (0  ^ kh)] = to_tf32(v.x);
            smf[vb + (8  ^ kh)] = to_tf32(v.y);
            smf[vb + (16 ^ kh)] = to_tf32(v.z);
            smf[vb + (24 ^ kh)] = to_tf32(v.w);
        }
        __syncthreads();

        // ---- S = Q K^T : 16 k-steps x 8 n-tiles per warp ----
        float sacc[8][4];
        #pragma unroll
        for (int n = 0; n < 8; n++)
            #pragma unroll
            for (int e = 0; e < 4; e++) sacc[n][e] = 0.0f;

        #pragma unroll
        for (int ks = 0; ks < 16; ks++) {
            int ab = Q_OFF + ks * QS_KS + (wm0 + qd) * 8 + 2 * qr;
            float2 aL = *(const float2*)(smf + ab);        // {a0, a2}
            float2 aH = *(const float2*)(smf + ab + 64);   // {a1, a3} (rows +8)
            uint32_t A0 = __float_as_uint(aL.x), A1 = __float_as_uint(aH.x);
            uint32_t A2 = __float_as_uint(aL.y), A3 = __float_as_uint(aH.y);
            #pragma unroll
            for (int nt = 0; nt < 8; nt++) {
                int bb = K_OFF + ks * KS_KS + (8 * nt + qd) * 8 + 2 * qr;
                float2 b = *(const float2*)(smf + bb);
                mma_tf32(sacc[nt], A0, A1, A2, A3,
                         __float_as_uint(b.x), __float_as_uint(b.y));
            }
        }

        // ---- softmax (fixed max) + store P in A-permuted layout ----
        {
            int prow = P_OFF + (wm0 + qd) * 8;
            int cl0 = 2 * qr, cl1 = 2 * qr + 1;
            int o0 = ((cl0 & 3) << 1) | (cl0 >> 2);
            int o1 = ((cl1 & 3) << 1) | (cl1 >> 2);
            #pragma unroll
            for (int nt = 0; nt < 8; nt++) {
                float p0 = exp2_fast(fmaxf(fmaf(sacc[nt][0], C1f, -M2f), -100.f));
                float p1 = exp2_fast(fmaxf(fmaf(sacc[nt][1], C1f, -M2f), -100.f));
                float p2 = exp2_fast(fmaxf(fmaf(sacc[nt][2], C1f, -M2f), -100.f));
                float p3 = exp2_fast(fmaxf(fmaf(sacc[nt][3], C1f, -M2f), -100.f));
                l0 += p0 + p1;
                l1 += p2 + p3;
                int pb = prow + nt * PS_KS;
                smf[pb + o0]      = to_tf32(p0);
                smf[pb + o1]      = to_tf32(p1);
                smf[pb + 64 + o0] = to_tf32(p2);
                smf[pb + 64 + o1] = to_tf32(p3);
            }
        }
        __syncwarp();   // P written cross-lane within this warp only

        // ---- O += P V : 8 k-steps (pos) x 16 n-tiles (d) per warp ----
        #pragma unroll
        for (int ksp = 0; ksp < 8; ksp++) {
            int ab = P_OFF + ksp * PS_KS + (wm0 + qd) * 8 + 2 * qr;
            float2 aL = *(const float2*)(smf + ab);
            float2 aH = *(const float2*)(smf + ab + 64);
            uint32_t A0 = __float_as_uint(aL.x), A1 = __float_as_uint(aH.x);
            uint32_t A2 = __float_as_uint(aL.y), A3 = __float_as_uint(aH.y);
            #pragma unroll
            for (int nt = 0; nt < 16; nt++) {
                int d  = 8 * nt + qd;
                int j  = d >> 2;
                int off = V_OFF + ksp * VS_KS
                        + ((d * 8) ^ ((j & 3) << 3))
                        + ((2 * qr) ^ (((j >> 2) & 3) << 1));
                float2 b = *(const float2*)(smf + off);
                mma_tf32(oacc[nt], A0, A1, A2, A3,
                         __float_as_uint(b.x), __float_as_uint(b.y));
            }
        }
    }

    // ---- epilogue: reduce l over quad, normalize, store ----
    l0 += __shfl_xor_sync(0xffffffffu, l0, 1);
    l0 += __shfl_xor_sync(0xffffffffu, l0, 2);
    l1 += __shfl_xor_sync(0xffffffffu, l1, 1);
    l1 += __shfl_xor_sync(0xffffffffu, l1, 2);
    float inv0 = 1.0f / l0, inv1 = 1.0f / l1;

    float* Or0 = Out + (bh * SL + q0 + wm0 + qd) * DH;
    float* Or1 = Or0 + 8 * DH;
    #pragma unroll
    for (int nt = 0; nt < 16; nt++) {
        float2 v0 = make_float2(oacc[nt][0] * inv0, oacc[nt][1] * inv0);
        float2 v1 = make_float2(oacc[nt][2] * inv1, oacc[nt][3] * inv1);
        *(float2*)(Or0 + 8 * nt + 2 * qr) = v0;
        *(float2*)(Or1 + 8 * nt + 2 * qr) = v1;
    }
}

extern "C" void kernel_launch(void* const* d_in, const int* in_sizes, int n_in,
                              void* d_out, int out_size)
{
    const float* q = (const float*)d_in[0];
    const float* k = (const float*)d_in[1];
    const float* v = (const float*)d_in[2];
    float* o = (float*)d_out;

    const int BH = in_sizes[0] / (SL * DH);   // 64

    cudaFuncSetAttribute(sdpa_mma_kernel,
                         cudaFuncAttributeMaxDynamicSharedMemorySize, SMEM_BYTES);
    dim3 grid(SL / BM, BH);
    sdpa_mma_kernel<<<grid, NT, SMEM_BYTES>>>(q, k, v, o);
}